// round 14
// baseline (speedup 1.0000x reference)
#include <cuda_runtime.h>
#include <math_constants.h>

typedef unsigned long long u64;

// Problem constants
#define BB 64
#define HH 224
#define WW 224
#define CC 196
#define HWP (HH*WW)
#define NEIGH 10

// Split-column band tiling with merged per-direction penalty maps
#define KIT   5             // iterations fused per launch
#define BR    16            // interior rows per band
#define TFY   26            // tile rows = BR + 2*KIT
#define BANDS 14            // 14*16 = 224 exactly
#define RPT   13            // rows per thread (TFY/2)
#define NT    224           // columns (threadIdx.x)
#define NH    2             // halves  (threadIdx.y)
#define NW    7             // warps per half
#define DYN_SMEM (4 * TFY * NT * (int)sizeof(float))   // mU+mD+mL+mR: 93184 B

// ---------------- static scratch ----------------
__device__ float g_mU[BB*HWP];   // wg + cpU[y]      (U pass)
__device__ float g_mD[BB*HWP];   // wg + cpU[y-1]    (D pass)
__device__ float g_mL[BB*HWP];   // wg + cpL[x]      (L pass)
__device__ float g_mR[BB*HWP];   // wg + cpL[x-1]    (R pass)
__device__ u64   g_pA[BB*HWP];   // packed (distbits<<32)|label
__device__ u64   g_pB[BB*HWP];
__device__ float g_minval[BB*CC];
__device__ int   g_minidx[BB*CC];
__device__ int   g_centi [BB*CC*2];

// ---------------- Phase 1a: window min + first argmin ----------------
__global__ void minima_kernel(const float* __restrict__ g) {
    int gw   = (blockIdx.x * blockDim.x + threadIdx.x) >> 5;
    int lane = threadIdx.x & 31;
    if (gw >= BB * CC) return;
    int b = gw / CC, c = gw - b * CC;
    int y0 = 8 + 16 * (c / 14);
    int x0 = 8 + 16 * (c % 14);
    int ymin = max(0, y0 - NEIGH), ymax = min(HH, y0 + NEIGH);
    int xmin = max(0, x0 - NEIGH), xmax = min(WW, x0 + NEIGH);
    int ww = xmax - xmin, n = (ymax - ymin) * ww;
    const float* gb = g + (size_t)b * HWP;

    float bv = CUDART_INF_F;
    int   bi = 0x7fffffff;
    for (int k = lane; k < n; k += 32) {
        int ky = k / ww;
        int f = (ymin + ky) * WW + xmin + (k - ky * ww);
        float v = gb[f];
        if (v < bv || (v == bv && f < bi)) { bv = v; bi = f; }
    }
    #pragma unroll
    for (int off = 16; off; off >>= 1) {
        float ov = __shfl_down_sync(0xffffffffu, bv, off);
        int   oi = __shfl_down_sync(0xffffffffu, bi, off);
        if (ov < bv || (ov == bv && oi < bi)) { bv = ov; bi = oi; }
    }
    if (lane == 0) { g_minval[gw] = bv; g_minidx[gw] = bi; }
}

// ---------------- Phase 1b: occupied-dedup, one warp per batch ----------------
__global__ void resolve_kernel(const float* __restrict__ g, float* __restrict__ out_cents) {
    __shared__ unsigned int occ[(HWP + 31) / 32];
    int b    = blockIdx.x;
    int lane = threadIdx.x;
    for (int i = lane; i < (HWP + 31) / 32; i += 32) occ[i] = 0u;
    __syncwarp();
    const float* gb = g + (size_t)b * HWP;

    for (int c = 0; c < CC; c++) {
        float mv = g_minval[b * CC + c];
        int   mi = g_minidx[b * CC + c];
        int y0c = 8 + 16 * (c / 14);
        int x0c = 8 + 16 * (c % 14);
        bool isocc = (occ[mi >> 5] >> (mi & 31)) & 1u;
        int  chosen = mi;
        bool found  = true;
        if (isocc) {
            found = false;
            int ymin = max(0, y0c - NEIGH), ymax = min(HH, y0c + NEIGH);
            int xmin = max(0, x0c - NEIGH), xmax = min(WW, x0c + NEIGH);
            int wwid = xmax - xmin, n = (ymax - ymin) * wwid;
            for (int base = 0; base < n; base += 32) {
                int k = base + lane;
                bool m = false; int f = 0;
                if (k < n) {
                    int ky = k / wwid;
                    f = (ymin + ky) * WW + xmin + (k - ky * wwid);
                    m = (gb[f] == mv) && !((occ[f >> 5] >> (f & 31)) & 1u);
                }
                unsigned bal = __ballot_sync(0xffffffffu, m);
                if (bal) {
                    chosen = __shfl_sync(0xffffffffu, f, __ffs(bal) - 1);
                    found = true;
                    break;
                }
            }
        }
        int cy, cx;
        if (found) {
            if (lane == 0) occ[chosen >> 5] |= 1u << (chosen & 31);
            cy = chosen / WW; cx = chosen - cy * WW;
        } else { cy = y0c; cx = x0c; }
        __syncwarp();
        if (lane == 0) {
            g_centi[(b * CC + c) * 2 + 0] = cy;
            g_centi[(b * CC + c) * 2 + 1] = cx;
            out_cents[(b * CC + c) * 2 + 0] = (float)cy;
            out_cents[(b * CC + c) * 2 + 1] = (float)cx;
        }
    }
}

// ---------------- Phase 2: merged maps + init (fused) ----------------
__global__ void maps_kernel(const float* __restrict__ xin, const float* __restrict__ g) {
    int i = blockIdx.x * blockDim.x + threadIdx.x;
    if (i >= BB * HWP) return;
    int b = i / HWP;
    int r = i - b * HWP;
    int y = r / WW;
    int x = r - y * WW;

    float gv = g[i];
    float t = gv * gv;
    float wg = (t * t) * 10.0f;

    const float* cb = xin + (size_t)b * 3 * HWP;
    int yS = (y + 1 == HH) ? 0 : y + 1;
    int yN = (y == 0) ? HH - 1 : y - 1;
    int xE = (x + 1 == WW) ? 0 : x + 1;
    int xW = (x == 0) ? WW - 1 : x - 1;
    int rS = yS * WW + x, rN = yN * WW + x;
    int rE = y * WW + xE, rW = y * WW + xW;
    float sS = 0.f, sN = 0.f, sE = 0.f, sW = 0.f;
    #pragma unroll
    for (int ch = 0; ch < 3; ch++) {
        float v = cb[ch * HWP + r];
        sS += fabsf(v - cb[ch * HWP + rS]);
        sN += fabsf(v - cb[ch * HWP + rN]);
        sE += fabsf(v - cb[ch * HWP + rE]);
        sW += fabsf(v - cb[ch * HWP + rW]);
    }
    g_mU[i] = wg + sS * 10.0f;   // cpU[y]
    g_mD[i] = wg + sN * 10.0f;   // cpU[y-1]
    g_mL[i] = wg + sE * 10.0f;   // cpL[x]
    g_mR[i] = wg + sW * 10.0f;   // cpL[x-1]

    g_pA[i] = (0x7f800000ull << 32) | 255ull;   // inf dist, sentinel label
}

// Parallel seed: one thread per (b,c). Collision-free (round-9 analysis).
__global__ void seed_kernel() {
    int i = blockIdx.x * blockDim.x + threadIdx.x;
    if (i >= BB * CC) return;
    int y = g_centi[i * 2 + 0];
    int x = g_centi[i * 2 + 1];
    int b = i / CC;
    g_pA[b * HWP + y * WW + x] = (u64)(unsigned)(i - b * CC);  // dist=0.0, label=c
}

// ---------------- Phase 3: KIT fused iterations, split columns ----------------
// Thread (x,h): column x, tile rows [h*RPT, h*RPT+RPT). dist (f32) + label
// (u32) in registers; merged penalty tiles in dynamic smem. Vertical passes:
// in-place register Jacobi with one seam value via smem. Horizontal passes:
// neighbor via __shfl within x-contiguous warps + warp-boundary smem.
// Update = 1 LDS + 1 FADD + FSETP + 2 SEL; float strict-< keeps reference
// tie semantics (merged-map add order differs by <=1 ulp from reference).
template <bool LAST>
__global__ void __launch_bounds__(NT*NH, 2) fused_reg_kernel(int ab, float* __restrict__ out_mask) {
    extern __shared__ float s_dyn[];
    float* mU = s_dyn;                  // [TFY][NT]
    float* mD = s_dyn + TFY * NT;
    float* mL = s_dyn + 2 * TFY * NT;
    float* mR = s_dyn + 3 * TFY * NT;

    __shared__ float    sLd[NH][NW][RPT];   // lane-0 state (pre-L)
    __shared__ unsigned sLl[NH][NW][RPT];
    __shared__ float    sRd[NH][NW][RPT];   // lane-31 state (post-L)
    __shared__ unsigned sRl[NH][NW][RPT];
    __shared__ float    seamUd[NT];         // h=1 row0 pre-U
    __shared__ unsigned seamUl[NT];
    __shared__ float    seamDd[NT];         // h=0 row RPT-1 post-U
    __shared__ unsigned seamDl[NT];

    const u64* pin  = ab ? g_pB : g_pA;
    u64*       pout = ab ? g_pA : g_pB;

    const int x    = threadIdx.x;
    const int h    = threadIdx.y;
    const int lane = x & 31;
    const int wq   = x >> 5;
    const int wqn  = (wq + 1) % NW;
    const int wqp  = (wq + NW - 1) % NW;
    const int band = blockIdx.x;
    const int b    = blockIdx.y;
    const int bb   = b * HWP;
    const int y0   = band * BR - KIT;
    const int tb   = h * RPT;

    float    dist[RPT];
    unsigned labu[RPT];

    // ---- load (coalesced) ----
    #pragma unroll
    for (int rl = 0; rl < RPT; rl++) {
        int t  = tb + rl;
        int gy = y0 + t; if (gy < 0) gy += HH; else if (gy >= HH) gy -= HH;
        int gi = bb + gy * WW + x;
        u64 pv = pin[gi];
        dist[rl] = __uint_as_float((unsigned)(pv >> 32));
        labu[rl] = (unsigned)pv;
        mU[t*NT + x] = g_mU[gi];
        mD[t*NT + x] = g_mD[gi];
        mL[t*NT + x] = g_mL[gi];
        mR[t*NT + x] = g_mR[gi];
    }
    // First cross-thread smem reads happen after the first __syncthreads.

    for (int i = 0; i < KIT; i++) {
        // ---- seam U write (pre-U h=1 row 0) ----
        if (h == 1) { seamUd[x] = dist[0]; seamUl[x] = labu[0]; }
        __syncthreads();

        // ---- U: tile rows [i, TFY-1-i), ascending, in place ----
        if (h == 0) {
            #pragma unroll
            for (int rl = 0; rl < RPT; rl++) {
                if (rl >= i) {
                    float nd; unsigned nl;
                    if (rl < RPT - 1) { nd = dist[rl + 1]; nl = labu[rl + 1]; }
                    else              { nd = seamUd[x];    nl = seamUl[x]; }
                    float wd = nd + mU[rl*NT + x];
                    if (wd < dist[rl]) { dist[rl] = wd; labu[rl] = nl; }
                }
            }
        } else {
            #pragma unroll
            for (int rl = 0; rl < RPT - 1; rl++) {
                if (rl < RPT - 1 - i) {
                    int t = RPT + rl;
                    float wd = dist[rl + 1] + mU[t*NT + x];
                    if (wd < dist[rl]) { dist[rl] = wd; labu[rl] = labu[rl + 1]; }
                }
            }
        }

        // ---- seam D write (post-U h=0 row RPT-1) ----
        if (h == 0) { seamDd[x] = dist[RPT - 1]; seamDl[x] = labu[RPT - 1]; }
        __syncthreads();

        // ---- D: tile rows [i+1, TFY-1-i), descending, in place ----
        if (h == 0) {
            #pragma unroll
            for (int rr = 0; rr < RPT - 1; rr++) {
                int rl = RPT - 1 - rr;
                if (rl >= i + 1) {
                    float wd = dist[rl - 1] + mD[rl*NT + x];
                    if (wd < dist[rl]) { dist[rl] = wd; labu[rl] = labu[rl - 1]; }
                }
            }
        } else {
            #pragma unroll
            for (int rr = 0; rr < RPT; rr++) {
                int rl = RPT - 1 - rr;
                if (rl < RPT - 1 - i) {
                    int t = RPT + rl;
                    float nd; unsigned nl;
                    if (rl > 0) { nd = dist[rl - 1]; nl = labu[rl - 1]; }
                    else        { nd = seamDd[x];    nl = seamDl[x]; }
                    float wd = nd + mD[t*NT + x];
                    if (wd < dist[rl]) { dist[rl] = wd; labu[rl] = nl; }
                }
            }
        }

        // ---- L boundary write (pre-L lane-0 state) ----
        if (lane == 0) {
            #pragma unroll
            for (int rl = 0; rl < RPT; rl++) { sLd[h][wq][rl] = dist[rl]; sLl[h][wq][rl] = labu[rl]; }
        }
        __syncthreads();
        // ---- L: reads column x+1 (old), rows [i+1, TFY-1-i) ----
        #pragma unroll
        for (int rl = 0; rl < RPT; rl++) {
            float    nd = __shfl_down_sync(0xffffffffu, dist[rl], 1);
            unsigned nl = __shfl_down_sync(0xffffffffu, labu[rl], 1);
            bool act = (h == 0) ? (rl >= i + 1) : (rl < RPT - 1 - i);
            if (act) {
                if (lane == 31) { nd = sLd[h][wqn][rl]; nl = sLl[h][wqn][rl]; }
                float wd = nd + mL[(tb + rl)*NT + x];
                if (wd < dist[rl]) { dist[rl] = wd; labu[rl] = nl; }
            }
        }
        // ---- R boundary write (post-L lane-31 state) ----
        if (lane == 31) {
            #pragma unroll
            for (int rl = 0; rl < RPT; rl++) { sRd[h][wq][rl] = dist[rl]; sRl[h][wq][rl] = labu[rl]; }
        }
        __syncthreads();
        // ---- R: reads column x-1 (post-L) ----
        #pragma unroll
        for (int rl = 0; rl < RPT; rl++) {
            float    nd = __shfl_up_sync(0xffffffffu, dist[rl], 1);
            unsigned nl = __shfl_up_sync(0xffffffffu, labu[rl], 1);
            bool act = (h == 0) ? (rl >= i + 1) : (rl < RPT - 1 - i);
            if (act) {
                if (lane == 0) { nd = sRd[h][wqp][rl]; nl = sRl[h][wqp][rl]; }
                float wd = nd + mR[(tb + rl)*NT + x];
                if (wd < dist[rl]) { dist[rl] = wd; labu[rl] = nl; }
            }
        }
    }

    // ---- store interior tile rows [KIT, KIT+BR) ----
    if (h == 0) {
        #pragma unroll
        for (int rl = KIT; rl < RPT; rl++) {
            int gi = bb + (band * BR + rl - KIT) * WW + x;
            if (LAST) out_mask[gi] = (labu[rl] == 255u) ? -1.0f : (float)labu[rl];
            else      pout[gi] = ((u64)__float_as_uint(dist[rl]) << 32) | (u64)labu[rl];
        }
    } else {
        #pragma unroll
        for (int rl = 0; rl < BR - (RPT - KIT); rl++) {
            int gi = bb + (band * BR + (RPT - KIT) + rl) * WW + x;
            if (LAST) out_mask[gi] = (labu[rl] == 255u) ? -1.0f : (float)labu[rl];
            else      pout[gi] = ((u64)__float_as_uint(dist[rl]) << 32) | (u64)labu[rl];
        }
    }
}

// ---------------- launch ----------------
extern "C" void kernel_launch(void* const* d_in, const int* in_sizes, int n_in,
                              void* d_out, int out_size) {
    const float* x;
    const float* g;
    if (in_sizes[0] == BB * 3 * HWP) { x = (const float*)d_in[0]; g = (const float*)d_in[1]; }
    else                             { x = (const float*)d_in[1]; g = (const float*)d_in[0]; }

    float* out       = (float*)d_out;
    float* out_cents = out;               // [B, C, 2] float32
    float* out_mask  = out + BB * CC * 2; // [B, H, W] float32

    const int NPX = BB * HWP;
    const int TPB = 256;
    const int GPX = (NPX + TPB - 1) / TPB;

    cudaFuncSetAttribute(fused_reg_kernel<false>,
                         cudaFuncAttributeMaxDynamicSharedMemorySize, DYN_SMEM);
    cudaFuncSetAttribute(fused_reg_kernel<true>,
                         cudaFuncAttributeMaxDynamicSharedMemorySize, DYN_SMEM);

    minima_kernel<<<(BB * CC * 32 + TPB - 1) / TPB, TPB>>>(g);
    resolve_kernel<<<BB, 32>>>(g, out_cents);
    maps_kernel<<<GPX, TPB>>>(x, g);
    seed_kernel<<<(BB * CC + TPB - 1) / TPB, TPB>>>();

    dim3 blk(NT, NH);
    int ab = 0;   // 0: current state in A
    const int NLAUNCH = 50 / KIT;   // 10
    for (int k = 0; k < NLAUNCH - 1; k++) {
        fused_reg_kernel<false><<<dim3(BANDS, BB), blk, DYN_SMEM>>>(ab, out_mask);
        ab ^= 1;
    }
    fused_reg_kernel<true><<<dim3(BANDS, BB), blk, DYN_SMEM>>>(ab, out_mask);
}

// round 15
// speedup vs baseline: 1.1040x; 1.1040x over previous
#include <cuda_runtime.h>
#include <math_constants.h>

typedef unsigned long long u64;

// Problem constants
#define BB 64
#define HH 224
#define WW 224
#define CC 196
#define HWP (HH*WW)
#define NEIGH 10

// Round-13 tiling (proven 962us), run persistently
#define KIT   5             // iterations per super-iteration
#define BR    28            // interior rows per band
#define TFY   38            // tile rows = BR + 2*KIT
#define BANDS 8             // 8*28 = 224 exactly
#define RPT   19            // rows per thread (TFY/2)
#define NT    224           // columns (threadIdx.x)
#define NH    2             // halves  (threadIdx.y)
#define NW    7             // warps per half
#define NLAB  5             // packed label regs (4 rows each)
#define DYN_SMEM (3 * TFY * NT * (int)sizeof(float))   // swg+scU+scL: 102144 B

#define NBLK   256          // persistent blocks (<= 296 resident: no deadlock)
#define NTILE  (BANDS*BB)   // 512 tiles, 2 per block
#define NSUPER 10           // 10 x KIT = 50 iterations

// ---------------- static scratch ----------------
__device__ float g_wg [BB*HWP];
__device__ float g_cpU[BB*HWP];
__device__ float g_cpL[BB*HWP];
__device__ u64   g_pA [BB*HWP];   // packed (distbits<<32)|label
__device__ u64   g_pB [BB*HWP];
__device__ float g_minval[BB*CC];
__device__ int   g_minidx[BB*CC];
__device__ int   g_centi [BB*CC*2];
__device__ int   g_barcnt;        // soft grid barrier state
__device__ int   g_barphase;

// ---------------- Phase 1a: window min + first argmin ----------------
__global__ void minima_kernel(const float* __restrict__ g) {
    int gw   = (blockIdx.x * blockDim.x + threadIdx.x) >> 5;
    int lane = threadIdx.x & 31;
    if (gw >= BB * CC) return;
    int b = gw / CC, c = gw - b * CC;
    int y0 = 8 + 16 * (c / 14);
    int x0 = 8 + 16 * (c % 14);
    int ymin = max(0, y0 - NEIGH), ymax = min(HH, y0 + NEIGH);
    int xmin = max(0, x0 - NEIGH), xmax = min(WW, x0 + NEIGH);
    int ww = xmax - xmin, n = (ymax - ymin) * ww;
    const float* gb = g + (size_t)b * HWP;

    float bv = CUDART_INF_F;
    int   bi = 0x7fffffff;
    for (int k = lane; k < n; k += 32) {
        int ky = k / ww;
        int f = (ymin + ky) * WW + xmin + (k - ky * ww);
        float v = gb[f];
        if (v < bv || (v == bv && f < bi)) { bv = v; bi = f; }
    }
    #pragma unroll
    for (int off = 16; off; off >>= 1) {
        float ov = __shfl_down_sync(0xffffffffu, bv, off);
        int   oi = __shfl_down_sync(0xffffffffu, bi, off);
        if (ov < bv || (ov == bv && oi < bi)) { bv = ov; bi = oi; }
    }
    if (lane == 0) { g_minval[gw] = bv; g_minidx[gw] = bi; }
}

// ---------------- Phase 1b: occupied-dedup, one warp per batch ----------------
__global__ void resolve_kernel(const float* __restrict__ g, float* __restrict__ out_cents) {
    __shared__ unsigned int occ[(HWP + 31) / 32];
    int b    = blockIdx.x;
    int lane = threadIdx.x;
    for (int i = lane; i < (HWP + 31) / 32; i += 32) occ[i] = 0u;
    __syncwarp();
    const float* gb = g + (size_t)b * HWP;

    for (int c = 0; c < CC; c++) {
        float mv = g_minval[b * CC + c];
        int   mi = g_minidx[b * CC + c];
        int y0c = 8 + 16 * (c / 14);
        int x0c = 8 + 16 * (c % 14);
        bool isocc = (occ[mi >> 5] >> (mi & 31)) & 1u;
        int  chosen = mi;
        bool found  = true;
        if (isocc) {
            found = false;
            int ymin = max(0, y0c - NEIGH), ymax = min(HH, y0c + NEIGH);
            int xmin = max(0, x0c - NEIGH), xmax = min(WW, x0c + NEIGH);
            int wwid = xmax - xmin, n = (ymax - ymin) * wwid;
            for (int base = 0; base < n; base += 32) {
                int k = base + lane;
                bool m = false; int f = 0;
                if (k < n) {
                    int ky = k / wwid;
                    f = (ymin + ky) * WW + xmin + (k - ky * wwid);
                    m = (gb[f] == mv) && !((occ[f >> 5] >> (f & 31)) & 1u);
                }
                unsigned bal = __ballot_sync(0xffffffffu, m);
                if (bal) {
                    chosen = __shfl_sync(0xffffffffu, f, __ffs(bal) - 1);
                    found = true;
                    break;
                }
            }
        }
        int cy, cx;
        if (found) {
            if (lane == 0) occ[chosen >> 5] |= 1u << (chosen & 31);
            cy = chosen / WW; cx = chosen - cy * WW;
        } else { cy = y0c; cx = x0c; }
        __syncwarp();
        if (lane == 0) {
            g_centi[(b * CC + c) * 2 + 0] = cy;
            g_centi[(b * CC + c) * 2 + 1] = cx;
            out_cents[(b * CC + c) * 2 + 0] = (float)cy;
            out_cents[(b * CC + c) * 2 + 1] = (float)cx;
        }
    }
}

// ---------------- Phase 2: maps + packed init (fused) ----------------
__global__ void maps_kernel(const float* __restrict__ xin, const float* __restrict__ g) {
    int i = blockIdx.x * blockDim.x + threadIdx.x;
    if (i >= BB * HWP) return;
    int b = i / HWP;
    int r = i - b * HWP;
    int y = r / WW;
    int x = r - y * WW;

    float gv = g[i];
    float t = gv * gv;
    g_wg[i] = (t * t) * 10.0f;

    const float* cb = xin + (size_t)b * 3 * HWP;
    int yn = (y + 1 == HH) ? 0 : y + 1;
    int xn = (x + 1 == WW) ? 0 : x + 1;
    int rU = yn * WW + x;
    int rL = y * WW + xn;
    float su = 0.0f, sl = 0.0f;
    #pragma unroll
    for (int ch = 0; ch < 3; ch++) {
        float v = cb[ch * HWP + r];
        su += fabsf(v - cb[ch * HWP + rU]);
        sl += fabsf(v - cb[ch * HWP + rL]);
    }
    g_cpU[i] = su * 10.0f;
    g_cpL[i] = sl * 10.0f;

    g_pA[i] = (0x7f800000ull << 32) | 255ull;   // inf dist, sentinel label
}

// Parallel seed + barrier-state reset. Collision-free (round-9 analysis).
__global__ void seed_kernel() {
    int i = blockIdx.x * blockDim.x + threadIdx.x;
    if (i == 0) { g_barcnt = 0; g_barphase = 0; }
    if (i >= BB * CC) return;
    int y = g_centi[i * 2 + 0];
    int x = g_centi[i * 2 + 1];
    int b = i / CC;
    g_pA[b * HWP + y * WW + x] = (u64)(unsigned)(i - b * CC);  // dist=0, label=c
}

// ---------------- packed-label helpers ----------------
__device__ __forceinline__ unsigned getb(const unsigned* lab, int q) {
    return (lab[q >> 2] >> ((q & 3) * 8)) & 0xFFu;
}
__device__ __forceinline__ void setb(unsigned* lab, int q, unsigned v) {
    int sh = (q & 3) * 8;
    lab[q >> 2] = (lab[q >> 2] & ~(0xFFu << sh)) | (v << sh);
}

// ---------------- Phase 3: persistent kernel, 10 super-iterations ----------------
// 256 resident blocks, each owns 2 fixed (batch,band) tiles. Inner tile body
// is the round-13 kernel verbatim (exact (nd+wg)+cp order). Cross-block state
// (g_pA/g_pB) is accessed L2-only (__ldcg/__stcg) so the soft grid barrier
// (atomic counter + threadfence, reset by seed each replay) gives coherence.
__global__ void __launch_bounds__(NT*NH, 2) persist_kernel(float* __restrict__ out_mask) {
    extern __shared__ float s_dyn[];
    float* swg = s_dyn;                  // [TFY][NT]
    float* scU = s_dyn + TFY * NT;
    float* scL = s_dyn + 2 * TFY * NT;

    __shared__ float    sLd[NH][NW][RPT];
    __shared__ unsigned sLl[NH][NW][NLAB];
    __shared__ float    sRd[NH][NW][RPT];
    __shared__ unsigned sRl[NH][NW][NLAB];
    __shared__ float    seamUd[NT];
    __shared__ unsigned seamUl[NT];
    __shared__ float    seamDd[NT];
    __shared__ unsigned seamDl[NT];

    const int x    = threadIdx.x;
    const int h    = threadIdx.y;
    const int lane = x & 31;
    const int wq   = x >> 5;
    const int wqn  = (wq + 1) % NW;
    const int wqp  = (wq + NW - 1) % NW;
    const int xl   = (x == 0) ? WW - 1 : x - 1;
    const int tb   = h * RPT;

    for (int s = 0; s < NSUPER; s++) {
        const u64* pin  = (s & 1) ? g_pB : g_pA;
        u64*       pout = (s & 1) ? g_pA : g_pB;
        const bool last = (s == NSUPER - 1);

        for (int rep = 0; rep < 2; rep++) {
            const int tile = blockIdx.x + rep * NBLK;
            const int band = tile & (BANDS - 1);
            const int b    = tile >> 3;
            const int bb   = b * HWP;
            const int y0   = band * BR - KIT;

            __syncthreads();   // previous rep's smem readers are done

            float    dist[RPT];
            unsigned lab[NLAB];

            // ---- load tile ----
            #pragma unroll
            for (int rl = 0; rl < RPT; rl++) {
                int t  = tb + rl;
                int gy = y0 + t; if (gy < 0) gy += HH; else if (gy >= HH) gy -= HH;
                int gi = bb + gy * WW + x;
                u64 pv = __ldcg(&pin[gi]);
                dist[rl] = __uint_as_float((unsigned)(pv >> 32));
                unsigned lv = (unsigned)pv & 0xFFu;
                if ((rl & 3) == 0) lab[rl >> 2] = lv;
                else               lab[rl >> 2] |= lv << ((rl & 3) * 8);
                swg[t*NT + x] = g_wg [gi];
                scU[t*NT + x] = g_cpU[gi];
                scL[t*NT + x] = g_cpL[gi];
            }

            for (int i = 0; i < KIT; i++) {
                // ---- seam U write (pre-U h=1 row 0) ----
                if (h == 1) { seamUd[x] = dist[0]; seamUl[x] = getb(lab, 0); }
                __syncthreads();
                // ---- U: tile rows [i, TFY-1-i), ascending, in place ----
                if (h == 0) {
                    #pragma unroll
                    for (int rl = 0; rl < RPT; rl++) {
                        if (rl >= i) {
                            float nd; unsigned nl;
                            if (rl < RPT - 1) { nd = dist[rl + 1]; nl = getb(lab, rl + 1); }
                            else              { nd = seamUd[x];    nl = seamUl[x]; }
                            float wd = (nd + swg[rl*NT + x]) + scU[rl*NT + x];
                            if (wd < dist[rl]) { dist[rl] = wd; setb(lab, rl, nl); }
                        }
                    }
                } else {
                    #pragma unroll
                    for (int rl = 0; rl < RPT - 1; rl++) {
                        if (rl < RPT - 1 - i) {
                            int t = RPT + rl;
                            float wd = (dist[rl + 1] + swg[t*NT + x]) + scU[t*NT + x];
                            if (wd < dist[rl]) { dist[rl] = wd; setb(lab, rl, getb(lab, rl + 1)); }
                        }
                    }
                }
                // ---- seam D write (post-U h=0 row RPT-1) ----
                if (h == 0) { seamDd[x] = dist[RPT - 1]; seamDl[x] = getb(lab, RPT - 1); }
                __syncthreads();
                // ---- D: tile rows [i+1, TFY-1-i), descending, in place ----
                if (h == 0) {
                    #pragma unroll
                    for (int rr = 0; rr < RPT - 1; rr++) {
                        int rl = RPT - 1 - rr;
                        if (rl >= i + 1) {
                            float wd = (dist[rl - 1] + swg[rl*NT + x]) + scU[(rl-1)*NT + x];
                            if (wd < dist[rl]) { dist[rl] = wd; setb(lab, rl, getb(lab, rl - 1)); }
                        }
                    }
                } else {
                    #pragma unroll
                    for (int rr = 0; rr < RPT; rr++) {
                        int rl = RPT - 1 - rr;
                        if (rl < RPT - 1 - i) {
                            int t = RPT + rl;
                            float nd; unsigned nl;
                            if (rl > 0) { nd = dist[rl - 1]; nl = getb(lab, rl - 1); }
                            else        { nd = seamDd[x];    nl = seamDl[x]; }
                            float wd = (nd + swg[t*NT + x]) + scU[(t-1)*NT + x];
                            if (wd < dist[rl]) { dist[rl] = wd; setb(lab, rl, nl); }
                        }
                    }
                }
                // ---- L boundary write (pre-L lane-0 state) ----
                if (lane == 0) {
                    #pragma unroll
                    for (int rl = 0; rl < RPT; rl++) sLd[h][wq][rl] = dist[rl];
                    #pragma unroll
                    for (int k = 0; k < NLAB; k++)   sLl[h][wq][k] = lab[k];
                }
                __syncthreads();
                // ---- L: reads column x+1 (old), rows [i+1, TFY-1-i) ----
                {
                    unsigned nlab[NLAB];
                    #pragma unroll
                    for (int k = 0; k < NLAB; k++) {
                        nlab[k] = __shfl_down_sync(0xffffffffu, lab[k], 1);
                        if (lane == 31) nlab[k] = sLl[h][wqn][k];
                    }
                    #pragma unroll
                    for (int rl = 0; rl < RPT; rl++) {
                        float nd = __shfl_down_sync(0xffffffffu, dist[rl], 1);
                        bool act = (h == 0) ? (rl >= i + 1) : (rl < RPT - 1 - i);
                        if (act) {
                            if (lane == 31) nd = sLd[h][wqn][rl];
                            int t = tb + rl;
                            float wd = (nd + swg[t*NT + x]) + scL[t*NT + x];
                            if (wd < dist[rl]) { dist[rl] = wd; setb(lab, rl, getb(nlab, rl)); }
                        }
                    }
                }
                // ---- R boundary write (post-L lane-31 state) ----
                if (lane == 31) {
                    #pragma unroll
                    for (int rl = 0; rl < RPT; rl++) sRd[h][wq][rl] = dist[rl];
                    #pragma unroll
                    for (int k = 0; k < NLAB; k++)   sRl[h][wq][k] = lab[k];
                }
                __syncthreads();
                // ---- R: reads column x-1 (post-L), cp = cpL[x-1] via smem ----
                {
                    unsigned nlab[NLAB];
                    #pragma unroll
                    for (int k = 0; k < NLAB; k++) {
                        nlab[k] = __shfl_up_sync(0xffffffffu, lab[k], 1);
                        if (lane == 0) nlab[k] = sRl[h][wqp][k];
                    }
                    #pragma unroll
                    for (int rl = 0; rl < RPT; rl++) {
                        float nd = __shfl_up_sync(0xffffffffu, dist[rl], 1);
                        bool act = (h == 0) ? (rl >= i + 1) : (rl < RPT - 1 - i);
                        if (act) {
                            if (lane == 0) nd = sRd[h][wqp][rl];
                            int t = tb + rl;
                            float wd = (nd + swg[t*NT + x]) + scL[t*NT + xl];
                            if (wd < dist[rl]) { dist[rl] = wd; setb(lab, rl, getb(nlab, rl)); }
                        }
                    }
                }
            }

            // ---- store interior tile rows [KIT, KIT+BR) ----
            if (h == 0) {
                #pragma unroll
                for (int rl = KIT; rl < RPT; rl++) {
                    int gi = bb + (band * BR + rl - KIT) * WW + x;
                    unsigned v = getb(lab, rl);
                    if (last) out_mask[gi] = (v == 255u) ? -1.0f : (float)v;
                    else      __stcg(&pout[gi], ((u64)__float_as_uint(dist[rl]) << 32) | (u64)v);
                }
            } else {
                #pragma unroll
                for (int rl = 0; rl < BR - (RPT - KIT); rl++) {
                    int gi = bb + (band * BR + (RPT - KIT) + rl) * WW + x;
                    unsigned v = getb(lab, rl);
                    if (last) out_mask[gi] = (v == 255u) ? -1.0f : (float)v;
                    else      __stcg(&pout[gi], ((u64)__float_as_uint(dist[rl]) << 32) | (u64)v);
                }
            }
        }

        // ---- soft grid barrier between super-iterations ----
        if (s < NSUPER - 1) {
            __syncthreads();
            if (x == 0 && h == 0) {
                __threadfence();
                int t = atomicAdd(&g_barcnt, 1);
                if (t == NBLK - 1) {
                    g_barcnt = 0;
                    __threadfence();
                    atomicExch(&g_barphase, s + 1);
                } else {
                    while (*(volatile int*)&g_barphase < s + 1) __nanosleep(64);
                }
            }
            __syncthreads();
        }
    }
}

// ---------------- launch ----------------
extern "C" void kernel_launch(void* const* d_in, const int* in_sizes, int n_in,
                              void* d_out, int out_size) {
    const float* x;
    const float* g;
    if (in_sizes[0] == BB * 3 * HWP) { x = (const float*)d_in[0]; g = (const float*)d_in[1]; }
    else                             { x = (const float*)d_in[1]; g = (const float*)d_in[0]; }

    float* out       = (float*)d_out;
    float* out_cents = out;               // [B, C, 2] float32
    float* out_mask  = out + BB * CC * 2; // [B, H, W] float32

    const int NPX = BB * HWP;
    const int TPB = 256;
    const int GPX = (NPX + TPB - 1) / TPB;

    cudaFuncSetAttribute(persist_kernel,
                         cudaFuncAttributeMaxDynamicSharedMemorySize, DYN_SMEM);

    minima_kernel<<<(BB * CC * 32 + TPB - 1) / TPB, TPB>>>(g);
    resolve_kernel<<<BB, 32>>>(g, out_cents);
    maps_kernel<<<GPX, TPB>>>(x, g);
    seed_kernel<<<(BB * CC + TPB - 1) / TPB, TPB>>>();

    persist_kernel<<<NBLK, dim3(NT, NH), DYN_SMEM>>>(out_mask);
}

// round 16
// speedup vs baseline: 1.1695x; 1.0593x over previous
#include <cuda_runtime.h>
#include <math_constants.h>

typedef unsigned long long u64;

// Problem constants
#define BB 64
#define HH 224
#define WW 224
#define CC 196
#define HWP (HH*WW)
#define NEIGH 10

// Split-column band tiling, occupancy-3 geometry
#define KIT   5             // iterations fused per launch
#define BR    14            // interior rows per band
#define TFY   24            // tile rows = BR + 2*KIT
#define BANDS 16            // 16*14 = 224 exactly
#define RPT   12            // rows per thread (TFY/2)
#define NT    224           // columns (threadIdx.x)
#define NH    2             // halves  (threadIdx.y)
#define NW    7             // warps per half
#define NLAB  3             // packed label regs (4 rows each)
#define DYN_SMEM (3 * TFY * NT * (int)sizeof(float))   // swg+scU+scL: 64512 B

// ---------------- static scratch ----------------
__device__ float         g_wg [BB*HWP];
__device__ float         g_cpU[BB*HWP];
__device__ float         g_cpL[BB*HWP];
__device__ float         g_dA [BB*HWP];
__device__ float         g_dB [BB*HWP];
__device__ unsigned char g_lA [BB*HWP];
__device__ unsigned char g_lB [BB*HWP];
__device__ float         g_minval[BB*CC];
__device__ int           g_minidx[BB*CC];
__device__ int           g_centi [BB*CC*2];

// ---------------- Phase 1a: window min + first argmin ----------------
__global__ void minima_kernel(const float* __restrict__ g) {
    int gw   = (blockIdx.x * blockDim.x + threadIdx.x) >> 5;
    int lane = threadIdx.x & 31;
    if (gw >= BB * CC) return;
    int b = gw / CC, c = gw - b * CC;
    int y0 = 8 + 16 * (c / 14);
    int x0 = 8 + 16 * (c % 14);
    int ymin = max(0, y0 - NEIGH), ymax = min(HH, y0 + NEIGH);
    int xmin = max(0, x0 - NEIGH), xmax = min(WW, x0 + NEIGH);
    int ww = xmax - xmin, n = (ymax - ymin) * ww;
    const float* gb = g + (size_t)b * HWP;

    float bv = CUDART_INF_F;
    int   bi = 0x7fffffff;
    for (int k = lane; k < n; k += 32) {
        int ky = k / ww;
        int f = (ymin + ky) * WW + xmin + (k - ky * ww);
        float v = gb[f];
        if (v < bv || (v == bv && f < bi)) { bv = v; bi = f; }
    }
    #pragma unroll
    for (int off = 16; off; off >>= 1) {
        float ov = __shfl_down_sync(0xffffffffu, bv, off);
        int   oi = __shfl_down_sync(0xffffffffu, bi, off);
        if (ov < bv || (ov == bv && oi < bi)) { bv = ov; bi = oi; }
    }
    if (lane == 0) { g_minval[gw] = bv; g_minidx[gw] = bi; }
}

// ---------------- Phase 1b: occupied-dedup, one warp per batch ----------------
__global__ void resolve_kernel(const float* __restrict__ g, float* __restrict__ out_cents) {
    __shared__ unsigned int occ[(HWP + 31) / 32];
    int b    = blockIdx.x;
    int lane = threadIdx.x;
    for (int i = lane; i < (HWP + 31) / 32; i += 32) occ[i] = 0u;
    __syncwarp();
    const float* gb = g + (size_t)b * HWP;

    for (int c = 0; c < CC; c++) {
        float mv = g_minval[b * CC + c];
        int   mi = g_minidx[b * CC + c];
        int y0c = 8 + 16 * (c / 14);
        int x0c = 8 + 16 * (c % 14);
        bool isocc = (occ[mi >> 5] >> (mi & 31)) & 1u;
        int  chosen = mi;
        bool found  = true;
        if (isocc) {
            found = false;
            int ymin = max(0, y0c - NEIGH), ymax = min(HH, y0c + NEIGH);
            int xmin = max(0, x0c - NEIGH), xmax = min(WW, x0c + NEIGH);
            int wwid = xmax - xmin, n = (ymax - ymin) * wwid;
            for (int base = 0; base < n; base += 32) {
                int k = base + lane;
                bool m = false; int f = 0;
                if (k < n) {
                    int ky = k / wwid;
                    f = (ymin + ky) * WW + xmin + (k - ky * wwid);
                    m = (gb[f] == mv) && !((occ[f >> 5] >> (f & 31)) & 1u);
                }
                unsigned bal = __ballot_sync(0xffffffffu, m);
                if (bal) {
                    chosen = __shfl_sync(0xffffffffu, f, __ffs(bal) - 1);
                    found = true;
                    break;
                }
            }
        }
        int cy, cx;
        if (found) {
            if (lane == 0) occ[chosen >> 5] |= 1u << (chosen & 31);
            cy = chosen / WW; cx = chosen - cy * WW;
        } else { cy = y0c; cx = x0c; }
        __syncwarp();
        if (lane == 0) {
            g_centi[(b * CC + c) * 2 + 0] = cy;
            g_centi[(b * CC + c) * 2 + 1] = cx;
            out_cents[(b * CC + c) * 2 + 0] = (float)cy;
            out_cents[(b * CC + c) * 2 + 1] = (float)cx;
        }
    }
}

// ---------------- Phase 2: maps + init (fused) ----------------
__global__ void maps_kernel(const float* __restrict__ xin, const float* __restrict__ g) {
    int i = blockIdx.x * blockDim.x + threadIdx.x;
    if (i >= BB * HWP) return;
    int b = i / HWP;
    int r = i - b * HWP;
    int y = r / WW;
    int x = r - y * WW;

    float gv = g[i];
    float t = gv * gv;
    g_wg[i] = (t * t) * 10.0f;

    const float* cb = xin + (size_t)b * 3 * HWP;
    int yn = (y + 1 == HH) ? 0 : y + 1;
    int xn = (x + 1 == WW) ? 0 : x + 1;
    int rU = yn * WW + x;
    int rL = y * WW + xn;
    float su = 0.0f, sl = 0.0f;
    #pragma unroll
    for (int ch = 0; ch < 3; ch++) {
        float v = cb[ch * HWP + r];
        su += fabsf(v - cb[ch * HWP + rU]);
        sl += fabsf(v - cb[ch * HWP + rL]);
    }
    g_cpU[i] = su * 10.0f;
    g_cpL[i] = sl * 10.0f;

    g_dA[i] = CUDART_INF_F;     // init fused here
    g_lA[i] = 255;
}

// Parallel seed: one thread per (b,c). Collision-free (round-9 analysis).
__global__ void seed_kernel() {
    int i = blockIdx.x * blockDim.x + threadIdx.x;
    if (i >= BB * CC) return;
    int y = g_centi[i * 2 + 0];
    int x = g_centi[i * 2 + 1];
    int b = i / CC;
    int idx = b * HWP + y * WW + x;
    g_dA[idx] = 0.0f;
    g_lA[idx] = (unsigned char)(i - b * CC);
}

// ---------------- packed-label helpers ----------------
__device__ __forceinline__ unsigned getb(const unsigned* lab, int q) {
    return (lab[q >> 2] >> ((q & 3) * 8)) & 0xFFu;
}
__device__ __forceinline__ void setb(unsigned* lab, int q, unsigned v) {
    int sh = (q & 3) * 8;
    lab[q >> 2] = (lab[q >> 2] & ~(0xFFu << sh)) | (v << sh);
}

// ---------------- Phase 3: KIT fused iterations, split columns, occ3 ----------------
// Thread (x,h): column x, tile rows [h*RPT, h*RPT+RPT). dist+labels in regs;
// wg/cpU/cpL tiles in dynamic smem. Vertical passes: in-place register Jacobi
// with one seam value via smem. Horizontal passes: neighbor via __shfl within
// x-contiguous warps + warp-boundary smem. Exact reference order (nd+wg)+cp.
template <bool LAST>
__global__ void __launch_bounds__(NT*NH, 3) fused_reg_kernel(int ab, float* __restrict__ out_mask) {
    extern __shared__ float s_dyn[];
    float* swg = s_dyn;                  // [TFY][NT]
    float* scU = s_dyn + TFY * NT;
    float* scL = s_dyn + 2 * TFY * NT;

    __shared__ float    sLd[NH][NW][RPT];   // lane-0 state (pre-L)
    __shared__ unsigned sLl[NH][NW][NLAB];
    __shared__ float    sRd[NH][NW][RPT];   // lane-31 state (post-L)
    __shared__ unsigned sRl[NH][NW][NLAB];
    __shared__ float    seamUd[NT];         // h=1 row0 pre-U
    __shared__ unsigned seamUl[NT];
    __shared__ float    seamDd[NT];         // h=0 row RPT-1 post-U
    __shared__ unsigned seamDl[NT];

    const float*         din  = ab ? g_dB : g_dA;
    float*               dout = ab ? g_dA : g_dB;
    const unsigned char* lin  = ab ? g_lB : g_lA;
    unsigned char*       lout = ab ? g_lA : g_lB;

    const int x    = threadIdx.x;
    const int h    = threadIdx.y;
    const int lane = x & 31;
    const int wq   = x >> 5;
    const int wqn  = (wq + 1) % NW;
    const int wqp  = (wq + NW - 1) % NW;
    const int xl   = (x == 0) ? WW - 1 : x - 1;
    const int band = blockIdx.x;
    const int b    = blockIdx.y;
    const int bb   = b * HWP;
    const int y0   = band * BR - KIT;
    const int tb   = h * RPT;

    float    dist[RPT];
    unsigned lab[NLAB];

    // ---- load (coalesced) ----
    #pragma unroll
    for (int rl = 0; rl < RPT; rl++) {
        int t  = tb + rl;
        int gy = y0 + t; if (gy < 0) gy += HH; else if (gy >= HH) gy -= HH;
        int gi = bb + gy * WW + x;
        dist[rl]      = din[gi];
        swg[t*NT + x] = g_wg [gi];
        scU[t*NT + x] = g_cpU[gi];
        scL[t*NT + x] = g_cpL[gi];
        unsigned lv = lin[gi];
        if ((rl & 3) == 0) lab[rl >> 2] = lv;
        else               lab[rl >> 2] |= lv << ((rl & 3) * 8);
    }
    // First cross-thread smem reads happen after the first __syncthreads.

    for (int i = 0; i < KIT; i++) {
        // ---- seam U write (pre-U h=1 row 0) ----
        if (h == 1) { seamUd[x] = dist[0]; seamUl[x] = getb(lab, 0); }
        __syncthreads();
        // ---- U: tile rows [i, TFY-1-i), ascending, in place ----
        if (h == 0) {
            #pragma unroll
            for (int rl = 0; rl < RPT; rl++) {
                if (rl >= i) {
                    float nd; unsigned nl;
                    if (rl < RPT - 1) { nd = dist[rl + 1]; nl = getb(lab, rl + 1); }
                    else              { nd = seamUd[x];    nl = seamUl[x]; }
                    float wd = (nd + swg[rl*NT + x]) + scU[rl*NT + x];
                    if (wd < dist[rl]) { dist[rl] = wd; setb(lab, rl, nl); }
                }
            }
        } else {
            #pragma unroll
            for (int rl = 0; rl < RPT - 1; rl++) {
                if (rl < RPT - 1 - i) {
                    int t = RPT + rl;
                    float wd = (dist[rl + 1] + swg[t*NT + x]) + scU[t*NT + x];
                    if (wd < dist[rl]) { dist[rl] = wd; setb(lab, rl, getb(lab, rl + 1)); }
                }
            }
        }
        // ---- seam D write (post-U h=0 row RPT-1) ----
        if (h == 0) { seamDd[x] = dist[RPT - 1]; seamDl[x] = getb(lab, RPT - 1); }
        __syncthreads();
        // ---- D: tile rows [i+1, TFY-1-i), descending, in place ----
        if (h == 0) {
            #pragma unroll
            for (int rr = 0; rr < RPT - 1; rr++) {
                int rl = RPT - 1 - rr;
                if (rl >= i + 1) {
                    float wd = (dist[rl - 1] + swg[rl*NT + x]) + scU[(rl-1)*NT + x];
                    if (wd < dist[rl]) { dist[rl] = wd; setb(lab, rl, getb(lab, rl - 1)); }
                }
            }
        } else {
            #pragma unroll
            for (int rr = 0; rr < RPT; rr++) {
                int rl = RPT - 1 - rr;
                if (rl < RPT - 1 - i) {
                    int t = RPT + rl;
                    float nd; unsigned nl;
                    if (rl > 0) { nd = dist[rl - 1]; nl = getb(lab, rl - 1); }
                    else        { nd = seamDd[x];    nl = seamDl[x]; }
                    float wd = (nd + swg[t*NT + x]) + scU[(t-1)*NT + x];
                    if (wd < dist[rl]) { dist[rl] = wd; setb(lab, rl, nl); }
                }
            }
        }
        // ---- L boundary write (pre-L lane-0 state) ----
        if (lane == 0) {
            #pragma unroll
            for (int rl = 0; rl < RPT; rl++) sLd[h][wq][rl] = dist[rl];
            #pragma unroll
            for (int k = 0; k < NLAB; k++)   sLl[h][wq][k] = lab[k];
        }
        __syncthreads();
        // ---- L: reads column x+1 (old), rows [i+1, TFY-1-i) ----
        {
            unsigned nlab[NLAB];
            #pragma unroll
            for (int k = 0; k < NLAB; k++) {
                nlab[k] = __shfl_down_sync(0xffffffffu, lab[k], 1);
                if (lane == 31) nlab[k] = sLl[h][wqn][k];
            }
            #pragma unroll
            for (int rl = 0; rl < RPT; rl++) {
                float nd = __shfl_down_sync(0xffffffffu, dist[rl], 1);
                bool act = (h == 0) ? (rl >= i + 1) : (rl < RPT - 1 - i);
                if (act) {
                    if (lane == 31) nd = sLd[h][wqn][rl];
                    int t = tb + rl;
                    float wd = (nd + swg[t*NT + x]) + scL[t*NT + x];
                    if (wd < dist[rl]) { dist[rl] = wd; setb(lab, rl, getb(nlab, rl)); }
                }
            }
        }
        // ---- R boundary write (post-L lane-31 state) ----
        if (lane == 31) {
            #pragma unroll
            for (int rl = 0; rl < RPT; rl++) sRd[h][wq][rl] = dist[rl];
            #pragma unroll
            for (int k = 0; k < NLAB; k++)   sRl[h][wq][k] = lab[k];
        }
        __syncthreads();
        // ---- R: reads column x-1 (post-L), cp = cpL[x-1] via smem ----
        {
            unsigned nlab[NLAB];
            #pragma unroll
            for (int k = 0; k < NLAB; k++) {
                nlab[k] = __shfl_up_sync(0xffffffffu, lab[k], 1);
                if (lane == 0) nlab[k] = sRl[h][wqp][k];
            }
            #pragma unroll
            for (int rl = 0; rl < RPT; rl++) {
                float nd = __shfl_up_sync(0xffffffffu, dist[rl], 1);
                bool act = (h == 0) ? (rl >= i + 1) : (rl < RPT - 1 - i);
                if (act) {
                    if (lane == 0) nd = sRd[h][wqp][rl];
                    int t = tb + rl;
                    float wd = (nd + swg[t*NT + x]) + scL[t*NT + xl];
                    if (wd < dist[rl]) { dist[rl] = wd; setb(lab, rl, getb(nlab, rl)); }
                }
            }
        }
    }

    // ---- store interior tile rows [KIT, KIT+BR) ----
    if (h == 0) {
        #pragma unroll
        for (int rl = KIT; rl < RPT; rl++) {
            int gi = bb + (band * BR + rl - KIT) * WW + x;
            unsigned v = getb(lab, rl);
            if (LAST) out_mask[gi] = (v == 255u) ? -1.0f : (float)v;
            else      { dout[gi] = dist[rl]; lout[gi] = (unsigned char)v; }
        }
    } else {
        #pragma unroll
        for (int rl = 0; rl < BR - (RPT - KIT); rl++) {
            int gi = bb + (band * BR + (RPT - KIT) + rl) * WW + x;
            unsigned v = getb(lab, rl);
            if (LAST) out_mask[gi] = (v == 255u) ? -1.0f : (float)v;
            else      { dout[gi] = dist[rl]; lout[gi] = (unsigned char)v; }
        }
    }
}

// ---------------- launch ----------------
extern "C" void kernel_launch(void* const* d_in, const int* in_sizes, int n_in,
                              void* d_out, int out_size) {
    const float* x;
    const float* g;
    if (in_sizes[0] == BB * 3 * HWP) { x = (const float*)d_in[0]; g = (const float*)d_in[1]; }
    else                             { x = (const float*)d_in[1]; g = (const float*)d_in[0]; }

    float* out       = (float*)d_out;
    float* out_cents = out;               // [B, C, 2] float32
    float* out_mask  = out + BB * CC * 2; // [B, H, W] float32

    const int NPX = BB * HWP;
    const int TPB = 256;
    const int GPX = (NPX + TPB - 1) / TPB;

    cudaFuncSetAttribute(fused_reg_kernel<false>,
                         cudaFuncAttributeMaxDynamicSharedMemorySize, DYN_SMEM);
    cudaFuncSetAttribute(fused_reg_kernel<true>,
                         cudaFuncAttributeMaxDynamicSharedMemorySize, DYN_SMEM);

    minima_kernel<<<(BB * CC * 32 + TPB - 1) / TPB, TPB>>>(g);
    resolve_kernel<<<BB, 32>>>(g, out_cents);
    maps_kernel<<<GPX, TPB>>>(x, g);
    seed_kernel<<<(BB * CC + TPB - 1) / TPB, TPB>>>();

    dim3 blk(NT, NH);
    int ab = 0;   // 0: current state in A
    const int NLAUNCH = 50 / KIT;   // 10
    for (int k = 0; k < NLAUNCH - 1; k++) {
        fused_reg_kernel<false><<<dim3(BANDS, BB), blk, DYN_SMEM>>>(ab, out_mask);
        ab ^= 1;
    }
    fused_reg_kernel<true><<<dim3(BANDS, BB), blk, DYN_SMEM>>>(ab, out_mask);
}